// round 1
// baseline (speedup 1.0000x reference)
#include <cuda_runtime.h>

// YOLO-v1 style loss reduction.
// prediction: [16384, 7, 7, 30] f32   (5*B + C, B=2, C=20)
// target:     [16384, 7, 7, 25] f32   (5 + C)
// out:        scalar f32
//
// Strategy: HBM-bound streaming reduction. 128 cells per block, staged
// into shared memory via coalesced float4 loads (per-cell strides 120B/100B
// would otherwise shatter coalescing), one thread per cell, block tree
// reduction, one float atomicAdd per block.

#define TPB        128
#define NCELLS     (16384 * 49)          // 802816
#define NBLOCKS    (NCELLS / TPB)        // 6272 (exact)
#define PRED_F     30
#define TARG_F     25
#define EPSV       1e-8f

__global__ void zero_out_kernel(float* out) { *out = 0.0f; }

__global__ void __launch_bounds__(TPB)
yolo_loss_kernel(const float* __restrict__ pred,
                 const float* __restrict__ targ,
                 float* __restrict__ out)
{
    __shared__ float sp[TPB * PRED_F];   // 15360 B
    __shared__ float st[TPB * TARG_F];   // 12800 B
    __shared__ float wsum[TPB / 32];

    const int tid = threadIdx.x;

    // ---- coalesced staging: tile bases are 16B-aligned for every block ----
    {
        const float4* gp = (const float4*)pred + (long long)blockIdx.x * (TPB * PRED_F / 4);
        const float4* gt = (const float4*)targ + (long long)blockIdx.x * (TPB * TARG_F / 4);
        float4* spv = (float4*)sp;
        float4* stv = (float4*)st;
        #pragma unroll
        for (int i = tid; i < TPB * PRED_F / 4; i += TPB) spv[i] = gp[i];
        #pragma unroll
        for (int i = tid; i < TPB * TARG_F / 4; i += TPB) stv[i] = gt[i];
    }
    __syncthreads();

    // ---- per-cell loss ----
    const int cell = blockIdx.x * TPB + tid;
    const int rc   = cell % 49;
    const float row = (float)(rc / 7);
    const float col = (float)(rc % 7);
    const float invS = 1.0f / 7.0f;

    const float* p = sp + tid * PRED_F;
    const float* t = st + tid * TARG_F;

    // ground-truth box -> corners
    const float gw = t[2], gh = t[3];
    const float gcx = (t[0] + col) * invS;
    const float gcy = (t[1] + row) * invS;
    const float gx1 = gcx - 0.5f * gw, gy1 = gcy - 0.5f * gh;
    const float gx2 = gcx + 0.5f * gw, gy2 = gcy + 0.5f * gh;
    const float ga  = fabsf(gw * gh);

    // IoU of both predicted boxes vs gt
    float iou0 = 0.0f, iou1 = 0.0f;
    #pragma unroll
    for (int b = 0; b < 2; b++) {
        const float* pb = p + 5 * b;
        const float w = pb[2], h = pb[3];
        const float cx = (pb[0] + col) * invS;
        const float cy = (pb[1] + row) * invS;
        const float x1 = cx - 0.5f * w, y1 = cy - 0.5f * h;
        const float x2 = cx + 0.5f * w, y2 = cy + 0.5f * h;
        const float ix = fminf(x2, gx2) - fmaxf(x1, gx1);
        const float iy = fminf(y2, gy2) - fmaxf(y1, gy1);
        const float inter = fmaxf(ix, 0.0f) * fmaxf(iy, 0.0f);
        const float pa = fabsf(w * h);
        const float v  = inter / (pa + ga - inter + EPSV);
        if (b == 0) iou0 = v; else iou1 = v;
    }
    // jnp.argmax: first max wins -> choose 1 only if strictly greater
    const int bi = (iou1 > iou0) ? 1 : 0;
    const float* s = p + 5 * bi;

    const float gc  = t[4];
    const bool  obj = (gc != 0.0f);

    float loss;
    if (obj) {
        const float dx = s[0] - t[0];
        const float dy = s[1] - t[1];
        const float center = dx * dx + dy * dy;

        const float pw = s[2], ph = s[3];
        const float sgnw = (pw > 0.0f) ? 1.0f : ((pw < 0.0f) ? -1.0f : 0.0f);
        const float sgnh = (ph > 0.0f) ? 1.0f : ((ph < 0.0f) ? -1.0f : 0.0f);
        const float sw = sgnw * sqrtf(fabsf(pw) + EPSV) - sqrtf(gw);
        const float sh = sgnh * sqrtf(fabsf(ph) + EPSV) - sqrtf(gh);
        const float dim = sw * sw + sh * sh;

        const float dc = s[4] - gc;
        const float conf = dc * dc;

        float cls = 0.0f;
        #pragma unroll
        for (int c = 0; c < 20; c++) {
            const float d = p[10 + c] - t[5 + c];
            cls += d * d;
        }
        loss = 5.0f * (center + dim) + conf + cls;   // class term gated by t[4]==1
    } else {
        const float d0 = p[4] - gc;
        const float d1 = p[9] - gc;
        loss = 0.5f * (d0 * d0 + d1 * d1);           // class term gated by t[4]==0
    }

    // ---- block reduction ----
    #pragma unroll
    for (int o = 16; o > 0; o >>= 1)
        loss += __shfl_down_sync(0xffffffffu, loss, o);
    if ((tid & 31) == 0) wsum[tid >> 5] = loss;
    __syncthreads();
    if (tid < (TPB / 32)) {
        float v = wsum[tid];
        #pragma unroll
        for (int o = (TPB / 64); o > 0; o >>= 1)
            v += __shfl_down_sync(0x0000000fu, v, o);
        if (tid == 0) atomicAdd(out, v);
    }
}

extern "C" void kernel_launch(void* const* d_in, const int* in_sizes, int n_in,
                              void* d_out, int out_size)
{
    const float* pred = (const float*)d_in[0];
    const float* targ = (const float*)d_in[1];
    float* out = (float*)d_out;

    zero_out_kernel<<<1, 1>>>(out);
    yolo_loss_kernel<<<NBLOCKS, TPB>>>(pred, targ, out);
}

// round 4
// speedup vs baseline: 1.1034x; 1.1034x over previous
#include <cuda_runtime.h>

// YOLO-v1 style loss reduction — cp.async double-buffered streaming version.
// prediction: [16384, 7, 7, 30] f32, target: [16384, 7, 7, 25] f32 -> scalar f32.
//
// Each block handles TILES=4 consecutive tiles of 128 cells. Tile t+1 is
// prefetched via cp.async.cg into the alternate smem buffer while tile t is
// computed, keeping HBM reads continuously in flight. Tile buffers live in
// DYNAMIC shared memory (static smem is capped at 48KB by ptxas).

#define TPB        128
#define TILES      4
#define NCELLS     (16384 * 49)              // 802816
#define NTILES     (NCELLS / TPB)            // 6272
#define NBLOCKS    (NTILES / TILES)          // 1568
#define PRED_F     30
#define TARG_F     25
#define PV4        (TPB * PRED_F / 4)        // 960 float4 per pred tile
#define TV4        (TPB * TARG_F / 4)        // 800 float4 per targ tile
#define PFLT       (TPB * PRED_F)            // 3840 floats per pred tile
#define TFLT       (TPB * TARG_F)            // 3200 floats per targ tile
#define DYN_BYTES  ((2 * PFLT + 2 * TFLT) * 4)   // 56320
#define EPSV       1e-8f

__global__ void zero_out_kernel(float* out) { *out = 0.0f; }

__device__ __forceinline__ void cp16(unsigned smem_addr, const float4* g) {
    asm volatile("cp.async.cg.shared.global [%0], [%1], 16;\n"
                 :: "r"(smem_addr), "l"(g));
}

__device__ __forceinline__ void prefetch_tile(int tile,
                                              unsigned spa, unsigned sta,
                                              const float4* gp_base,
                                              const float4* gt_base,
                                              int tid)
{
    const float4* gp = gp_base + (size_t)tile * PV4;
    const float4* gt = gt_base + (size_t)tile * TV4;
    #pragma unroll
    for (int i = tid; i < PV4; i += TPB) cp16(spa + i * 16u, gp + i);
    #pragma unroll
    for (int i = tid; i < TV4; i += TPB) cp16(sta + i * 16u, gt + i);
    asm volatile("cp.async.commit_group;\n");
}

__global__ void __launch_bounds__(TPB)
yolo_loss_kernel(const float* __restrict__ pred,
                 const float* __restrict__ targ,
                 float* __restrict__ out)
{
    extern __shared__ float dyn[];
    // layout: sp0 | sp1 | st0 | st1
    float* spbuf[2] = { dyn,              dyn + PFLT };
    float* stbuf[2] = { dyn + 2 * PFLT,   dyn + 2 * PFLT + TFLT };
    __shared__ float wsum[TPB / 32];

    const int tid = threadIdx.x;
    const float4* gp_base = (const float4*)pred;
    const float4* gt_base = (const float4*)targ;

    unsigned spa[2], sta[2];
    spa[0] = (unsigned)__cvta_generic_to_shared(spbuf[0]);
    spa[1] = (unsigned)__cvta_generic_to_shared(spbuf[1]);
    sta[0] = (unsigned)__cvta_generic_to_shared(stbuf[0]);
    sta[1] = (unsigned)__cvta_generic_to_shared(stbuf[1]);

    const int tile0 = blockIdx.x * TILES;
    prefetch_tile(tile0, spa[0], sta[0], gp_base, gt_base, tid);

    float acc = 0.0f;
    const float invS = 1.0f / 7.0f;

    #pragma unroll
    for (int t = 0; t < TILES; t++) {
        const int buf = t & 1;
        if (t + 1 < TILES) {
            prefetch_tile(tile0 + t + 1, spa[buf ^ 1], sta[buf ^ 1],
                          gp_base, gt_base, tid);
            asm volatile("cp.async.wait_group 1;\n");
        } else {
            asm volatile("cp.async.wait_group 0;\n");
        }
        __syncthreads();

        // ---- per-cell loss for tile t ----
        const int cell = (tile0 + t) * TPB + tid;
        const int rc   = cell % 49;
        const float row = (float)(rc / 7);
        const float col = (float)(rc % 7);

        const float* p  = spbuf[buf] + tid * PRED_F;
        const float* tt = stbuf[buf] + tid * TARG_F;

        const float gw = tt[2], gh = tt[3];
        const float gcx = (tt[0] + col) * invS;
        const float gcy = (tt[1] + row) * invS;
        const float gx1 = gcx - 0.5f * gw, gy1 = gcy - 0.5f * gh;
        const float gx2 = gcx + 0.5f * gw, gy2 = gcy + 0.5f * gh;
        const float ga  = fabsf(gw * gh);

        float iou0 = 0.0f, iou1 = 0.0f;
        #pragma unroll
        for (int b = 0; b < 2; b++) {
            const float* pb = p + 5 * b;
            const float w = pb[2], h = pb[3];
            const float cx = (pb[0] + col) * invS;
            const float cy = (pb[1] + row) * invS;
            const float x1 = cx - 0.5f * w, y1 = cy - 0.5f * h;
            const float x2 = cx + 0.5f * w, y2 = cy + 0.5f * h;
            const float ix = fminf(x2, gx2) - fmaxf(x1, gx1);
            const float iy = fminf(y2, gy2) - fmaxf(y1, gy1);
            const float inter = fmaxf(ix, 0.0f) * fmaxf(iy, 0.0f);
            const float pa = fabsf(w * h);
            const float v  = inter / (pa + ga - inter + EPSV);
            if (b == 0) iou0 = v; else iou1 = v;
        }
        const int bi = (iou1 > iou0) ? 1 : 0;     // argmax: first max wins
        const float* s = p + 5 * bi;

        const float gc  = tt[4];
        const bool  obj = (gc != 0.0f);

        float loss;
        if (obj) {
            const float dx = s[0] - tt[0];
            const float dy = s[1] - tt[1];
            const float center = dx * dx + dy * dy;

            const float pw = s[2], ph = s[3];
            const float sgnw = (pw > 0.0f) ? 1.0f : ((pw < 0.0f) ? -1.0f : 0.0f);
            const float sgnh = (ph > 0.0f) ? 1.0f : ((ph < 0.0f) ? -1.0f : 0.0f);
            const float swv = sgnw * sqrtf(fabsf(pw) + EPSV) - sqrtf(gw);
            const float shv = sgnh * sqrtf(fabsf(ph) + EPSV) - sqrtf(gh);
            const float dim = swv * swv + shv * shv;

            const float dc = s[4] - gc;
            float cls = 0.0f;
            #pragma unroll
            for (int c = 0; c < 20; c++) {
                const float d = p[10 + c] - tt[5 + c];
                cls += d * d;
            }
            loss = 5.0f * (center + dim) + dc * dc + cls;
        } else {
            const float d0 = p[4] - gc;
            const float d1 = p[9] - gc;
            loss = 0.5f * (d0 * d0 + d1 * d1);
        }
        acc += loss;

        __syncthreads();   // everyone done reading buf before it is refilled
    }

    // ---- block reduction ----
    #pragma unroll
    for (int o = 16; o > 0; o >>= 1)
        acc += __shfl_down_sync(0xffffffffu, acc, o);
    if ((tid & 31) == 0) wsum[tid >> 5] = acc;
    __syncthreads();
    if (tid < (TPB / 32)) {
        float v = wsum[tid];
        #pragma unroll
        for (int o = (TPB / 64); o > 0; o >>= 1)
            v += __shfl_down_sync(0x0000000fu, v, o);
        if (tid == 0) atomicAdd(out, v);
    }
}

extern "C" void kernel_launch(void* const* d_in, const int* in_sizes, int n_in,
                              void* d_out, int out_size)
{
    const float* pred = (const float*)d_in[0];
    const float* targ = (const float*)d_in[1];
    float* out = (float*)d_out;

    // Opt in to >48KB dynamic smem (host-side attribute, not a stream op —
    // safe under graph capture, idempotent, no allocation).
    cudaFuncSetAttribute(yolo_loss_kernel,
                         cudaFuncAttributeMaxDynamicSharedMemorySize,
                         DYN_BYTES);

    zero_out_kernel<<<1, 1>>>(out);
    yolo_loss_kernel<<<NBLOCKS, TPB, DYN_BYTES>>>(pred, targ, out);
}